// round 16
// baseline (speedup 1.0000x reference)
#include <cuda_runtime.h>

#define NPTS 32768
#define CDIM 128
#define NSAM 16
#define CSD  16
#define PAIRS (NPTS*NSAM)
#define FEPS 1e-5f

// ---------------- scratch (device globals; no allocation allowed) ----------
__device__ float g_q[NPTS*CDIM];
__device__ float g_k[NPTS*CDIM];
__device__ float g_v[NPTS*CDIM];
__device__ float g_prlin[PAIRS*3];
__device__ float g_w2[PAIRS*CSD];

__device__ float g_s1[3],    g_ss1[3],    g_scale1[3],    g_shift1[3];
__device__ float g_s2[CDIM], g_ss2[CDIM], g_scale2[CDIM], g_shift2[CDIM];
__device__ float g_s3[CSD],  g_ss3[CSD],  g_scale3[CSD],  g_shift3[CSD];
__device__ unsigned g_tk1, g_tk2, g_tk3;

__device__ __forceinline__ unsigned f2tf32(float v) {
    unsigned r; asm("cvt.rna.tf32.f32 %0, %1;" : "=r"(r) : "f"(v)); return r;
}
__device__ __forceinline__ void mma_tf32(float* acc, unsigned a0, unsigned a1,
                                         unsigned a2, unsigned a3,
                                         unsigned b0, unsigned b1) {
    asm volatile(
        "mma.sync.aligned.m16n8k8.row.col.f32.tf32.tf32.f32 "
        "{%0,%1,%2,%3}, {%4,%5,%6,%7}, {%8,%9}, {%0,%1,%2,%3};"
        : "+f"(acc[0]), "+f"(acc[1]), "+f"(acc[2]), "+f"(acc[3])
        : "r"(a0), "r"(a1), "r"(a2), "r"(a3), "r"(b0), "r"(b1));
}

// ---------------- K1: q,k,v projections via tf32 mma (single-pass all) ------
__global__ __launch_bounds__(128)
void k_proj_mma(const float* __restrict__ x,
                const float* __restrict__ Wq, const float* __restrict__ bq,
                const float* __restrict__ Wk, const float* __restrict__ bk,
                const float* __restrict__ Wv, const float* __restrict__ bv) {
    if (blockIdx.x == 0 && blockIdx.y == 0) {
        int tt = threadIdx.x;
        if (tt < 3)    { g_s1[tt] = 0.f; g_ss1[tt] = 0.f; }
        if (tt < CDIM) { g_s2[tt] = 0.f; g_ss2[tt] = 0.f; }
        if (tt < CSD)  { g_s3[tt] = 0.f; g_ss3[tt] = 0.f; }
        if (tt == 0) { g_tk1 = 0; g_tk2 = 0; g_tk3 = 0; }
    }

    const float* W; const float* b; float* out;
    if (blockIdx.y == 0)      { W = Wq; b = bq; out = g_q; }
    else if (blockIdx.y == 1) { W = Wk; b = bk; out = g_k; }
    else                      { W = Wv; b = bv; out = g_v; }

    __shared__ unsigned xs_hi[64*20];
    __shared__ unsigned ws_hi[128*20];

    int t = threadIdx.x;
    int lane = t & 31, w = t >> 5;
    int row0 = blockIdx.x * 64;
    int gr = lane >> 2;
    int gc = lane & 3;

    float acc[16][4];
#pragma unroll
    for (int nt = 0; nt < 16; nt++)
#pragma unroll
        for (int j = 0; j < 4; j++) acc[nt][j] = 0.f;

    for (int kb = 0; kb < 128; kb += 16) {
#pragma unroll
        for (int e = t; e < 64*16; e += 128) {
            int r = e >> 4, k = e & 15;
            xs_hi[r*20 + k] = f2tf32(x[(row0 + r)*128 + kb + k]);
        }
#pragma unroll
        for (int e = t; e < 128*16; e += 128) {
            int k = e >> 7, n = e & 127;
            ws_hi[n*20 + k] = f2tf32(W[(kb + k)*128 + n]);
        }
        __syncthreads();

#pragma unroll
        for (int ks = 0; ks < 2; ks++) {
            int k0 = ks*8;
            int ra = (w*16 + gr)*20 + k0 + gc;
            int rb = (w*16 + gr + 8)*20 + k0 + gc;
            unsigned ah0 = xs_hi[ra],     ah1 = xs_hi[rb];
            unsigned ah2 = xs_hi[ra + 4], ah3 = xs_hi[rb + 4];
#pragma unroll
            for (int nt = 0; nt < 16; nt++) {
                int nb = (nt*8 + gr)*20 + k0 + gc;
                unsigned bh0 = ws_hi[nb], bh1 = ws_hi[nb + 4];
                mma_tf32(acc[nt], ah0, ah1, ah2, ah3, bh0, bh1);
            }
        }
        __syncthreads();
    }

    int r0 = row0 + w*16 + gr;
#pragma unroll
    for (int nt = 0; nt < 16; nt++) {
        int col = nt*8 + gc*2;
        float b0v = b[col], b1v = b[col+1];
        float2 o0 = {acc[nt][0] + b0v, acc[nt][1] + b1v};
        float2 o1 = {acc[nt][2] + b0v, acc[nt][3] + b1v};
        *(float2*)&out[r0*128 + col]     = o0;
        *(float2*)&out[(r0+8)*128 + col] = o1;
    }
}

// ---------------- K2: prlin + BN1 stats + fused finalize --------------------
__global__ void k_prlin(const float* __restrict__ p, const int* __restrict__ idx,
                        const float* __restrict__ pW1, const float* __restrict__ pb1,
                        const float* __restrict__ g, const float* __restrict__ be) {
    float w00 = pW1[0], w01 = pW1[1], w02 = pW1[2];
    float w10 = pW1[3], w11 = pW1[4], w12 = pW1[5];
    float w20 = pW1[6], w21 = pW1[7], w22 = pW1[8];
    float b0 = pb1[0], b1 = pb1[1], b2 = pb1[2];

    float s[3]  = {0.f, 0.f, 0.f};
    float ss[3] = {0.f, 0.f, 0.f};

    int stride = gridDim.x * blockDim.x;
    for (int pair = blockIdx.x*blockDim.x + threadIdx.x; pair < PAIRS; pair += stride) {
        int n   = pair >> 4;
        int nbr = idx[pair];
        float d0 = p[nbr*3+0] - p[n*3+0];
        float d1 = p[nbr*3+1] - p[n*3+1];
        float d2 = p[nbr*3+2] - p[n*3+2];
        float v0 = b0 + d0*w00 + d1*w10 + d2*w20;
        float v1 = b1 + d0*w01 + d1*w11 + d2*w21;
        float v2 = b2 + d0*w02 + d1*w12 + d2*w22;
        g_prlin[pair*3+0] = v0;
        g_prlin[pair*3+1] = v1;
        g_prlin[pair*3+2] = v2;
        s[0] += v0; ss[0] += v0*v0;
        s[1] += v1; ss[1] += v1*v1;
        s[2] += v2; ss[2] += v2*v2;
    }

#pragma unroll
    for (int o = 16; o > 0; o >>= 1) {
#pragma unroll
        for (int j = 0; j < 3; j++) {
            s[j]  += __shfl_down_sync(0xffffffffu, s[j],  o);
            ss[j] += __shfl_down_sync(0xffffffffu, ss[j], o);
        }
    }
    __shared__ float part[8][6];
    int lane = threadIdx.x & 31, w = threadIdx.x >> 5;
    if (lane == 0) {
        part[w][0] = s[0];  part[w][1] = s[1];  part[w][2] = s[2];
        part[w][3] = ss[0]; part[w][4] = ss[1]; part[w][5] = ss[2];
    }
    __syncthreads();
    if (threadIdx.x < 6) {
        float tot = 0.f;
#pragma unroll
        for (int ww = 0; ww < 8; ww++) tot += part[ww][threadIdx.x];
        if (threadIdx.x < 3) atomicAdd(&g_s1[threadIdx.x], tot);
        else                 atomicAdd(&g_ss1[threadIdx.x - 3], tot);
    }
    __syncthreads();
    __shared__ bool is_last;
    if (threadIdx.x == 0) {
        __threadfence();
        is_last = (atomicAdd(&g_tk1, 1u) == gridDim.x - 1);
    }
    __syncthreads();
    if (is_last && threadIdx.x < 3) {
        __threadfence();
        int c = threadIdx.x;
        float cnt = (float)PAIRS;
        float mean = g_s1[c] / cnt;
        float var  = g_ss1[c] / cnt - mean*mean;
        float scv  = g[c] * rsqrtf(var + FEPS);
        g_scale1[c] = scv;
        g_shift1[c] = be[c] - mean*scv;
    }
}

// ---------------- K3: BN2 stats ----------------------------------------------
__global__ __launch_bounds__(256, 5)
void k_bn2stats(const int* __restrict__ idx,
                const float* __restrict__ pW2, const float* __restrict__ pb2,
                const float* __restrict__ g, const float* __restrict__ be) {
    int t = threadIdx.x, lane = t & 31, w = t >> 5;
    int wg = blockIdx.x*8 + w;
    int base = wg*32;

    __shared__ float hsm[8][32][3];
    __shared__ int   ism[8][32];

    float4 pw0  = *(const float4*)&pW2[0*CDIM + lane*4];
    float4 pw1  = *(const float4*)&pW2[1*CDIM + lane*4];
    float4 pw2v = *(const float4*)&pW2[2*CDIM + lane*4];
    float4 pbv  = *(const float4*)&pb2[lane*4];
    float sc0 = g_scale1[0], sc1 = g_scale1[1], sc2 = g_scale1[2];
    float sh0 = g_shift1[0], sh1 = g_shift1[1], sh2 = g_shift1[2];

    {
        int pair = base + lane;
        ism[w][lane] = idx[pair];
        hsm[w][lane][0] = fmaxf(g_prlin[pair*3+0]*sc0 + sh0, 0.f);
        hsm[w][lane][1] = fmaxf(g_prlin[pair*3+1]*sc1 + sh1, 0.f);
        hsm[w][lane][2] = fmaxf(g_prlin[pair*3+2]*sc2 + sh2, 0.f);
    }
    __syncwarp();

    const float4* kp = (const float4*)g_k;
    const float4* qp = (const float4*)g_q;

    float4 s4  = {0.f,0.f,0.f,0.f};
    float4 q4s = {0.f,0.f,0.f,0.f};

#pragma unroll
    for (int np = 0; np < 2; np++) {
        int n = (base >> 4) + np;
        float4 qq = qp[n*32 + lane];
        float4 b4;
        b4.x = pbv.x - qq.x; b4.y = pbv.y - qq.y;
        b4.z = pbv.z - qq.z; b4.w = pbv.w - qq.w;
#pragma unroll
        for (int s = 0; s < 16; s++) {
            int i   = np*16 + s;
            int nbr = ism[w][i];
            float h0 = hsm[w][i][0], h1 = hsm[w][i][1], h2 = hsm[w][i][2];
            float4 kk = kp[nbr*32 + lane];
            float wx = kk.x + b4.x + h0*pw0.x + h1*pw1.x + h2*pw2v.x;
            float wy = kk.y + b4.y + h0*pw0.y + h1*pw1.y + h2*pw2v.y;
            float wz = kk.z + b4.z + h0*pw0.z + h1*pw1.z + h2*pw2v.z;
            float ww = kk.w + b4.w + h0*pw0.w + h1*pw1.w + h2*pw2v.w;
            s4.x += wx; q4s.x += wx*wx;
            s4.y += wy; q4s.y += wy*wy;
            s4.z += wz; q4s.z += wz*wz;
            s4.w += ww; q4s.w += ww*ww;
        }
    }

    __shared__ float red[8][256];
    red[w][lane*4+0]     = s4.x;  red[w][lane*4+1]     = s4.y;
    red[w][lane*4+2]     = s4.z;  red[w][lane*4+3]     = s4.w;
    red[w][128+lane*4+0] = q4s.x; red[w][128+lane*4+1] = q4s.y;
    red[w][128+lane*4+2] = q4s.z; red[w][128+lane*4+3] = q4s.w;
    __syncthreads();
    float tot = 0.f;
#pragma unroll
    for (int ww = 0; ww < 8; ww++) tot += red[ww][t];
    if (t < 128) atomicAdd(&g_s2[t], tot);
    else         atomicAdd(&g_ss2[t-128], tot);

    __syncthreads();
    __shared__ bool is_last;
    if (t == 0) {
        __threadfence();
        is_last = (atomicAdd(&g_tk2, 1u) == gridDim.x - 1);
    }
    __syncthreads();
    if (is_last && t < CDIM) {
        __threadfence();
        float cnt = (float)PAIRS;
        float mean = g_s2[t] / cnt;
        float var  = g_ss2[t] / cnt - mean*mean;
        float scv  = g[t] * rsqrtf(var + FEPS);
        g_scale2[t] = scv;
        g_shift2[t] = be[t] - mean*scv;
    }
}

// ---------------- K4 (PROFILED): w2 — point-prefetched staging pipeline -----
// Half-split K (stride 68), coalesced float2 gather, folded BN2, fused
// n-tiles. Next point's idx/prlin LDGs issue during current point's MMAs;
// consumed (FMA+STS into double-buffered iA/hA) ~600 issues later.
__global__ __launch_bounds__(128, 6)
void k_w2(const int* __restrict__ idx,
          const float* __restrict__ pW2, const float* __restrict__ pb2,
          const float* __restrict__ wW1, const float* __restrict__ wb1,
          const float* __restrict__ g, const float* __restrict__ be) {
    __shared__ unsigned us[4*16*68];      // per-warp HALF u tile, stride 68
    __shared__ unsigned wt[2*16*68];      // wW1^T tf32, [half][j][c']
    __shared__ float hA[4][2][16][3];
    __shared__ int   iA[4][2][16];
    __shared__ float s3s[CSD], ss3s[CSD];

    int t = threadIdx.x, lane = t & 31, w = t >> 5;   // w: 0..3
    int gr = lane >> 2, gc = lane & 3;

    // stage wW1 transposed, split by half
    for (int e = t; e < 128*16; e += 128) {
        int c = e >> 4, j = e & 15;
        int h = c >> 6, cp = c & 63;
        wt[(h*16 + j)*68 + cp] = f2tf32(wW1[e]);
    }
    if (t < CSD) { s3s[t] = 0.f; ss3s[t] = 0.f; }

    // lane owns channels (h*64 + 2*lane, +1) per half; BN2 scale folded
    float2 PW0[2], PW1[2], PW2v[2], S2[2], PBH[2];
#pragma unroll
    for (int h = 0; h < 2; h++) {
        int c = h*64 + 2*lane;
        float2 s2 = *(const float2*)&g_scale2[c];
        float2 a;
        S2[h] = s2;
        a = *(const float2*)&pW2[0*CDIM + c];
        PW0[h] = make_float2(a.x*s2.x, a.y*s2.y);
        a = *(const float2*)&pW2[1*CDIM + c];
        PW1[h] = make_float2(a.x*s2.x, a.y*s2.y);
        a = *(const float2*)&pW2[2*CDIM + c];
        PW2v[h] = make_float2(a.x*s2.x, a.y*s2.y);
        float2 pb = *(const float2*)&pb2[c];
        float2 h2 = *(const float2*)&g_shift2[c];
        PBH[h] = make_float2(pb.x*s2.x + h2.x, pb.y*s2.y + h2.y);
    }
    float sc0 = g_scale1[0], sc1 = g_scale1[1], sc2 = g_scale1[2];
    float sh0 = g_shift1[0], sh1 = g_shift1[1], sh2 = g_shift1[2];

    float bcol[4];
    bcol[0] = wb1[gc*2];     bcol[1] = wb1[gc*2+1];
    bcol[2] = wb1[8+gc*2];   bcol[3] = wb1[8+gc*2+1];
    float ls[4]  = {0.f,0.f,0.f,0.f};
    float lss[4] = {0.f,0.f,0.f,0.f};

    unsigned* usw = &us[w*16*68];
    int n0 = blockIdx.x*16 + w*4;

    // prologue: stage point 0 into buf 0
    if (lane < 16) {
        int pair = n0*16 + lane;
        iA[w][0][lane] = idx[pair];
        hA[w][0][lane][0] = fmaxf(g_prlin[pair*3+0]*sc0 + sh0, 0.f);
        hA[w][0][lane][1] = fmaxf(g_prlin[pair*3+1]*sc1 + sh1, 0.f);
        hA[w][0][lane][2] = fmaxf(g_prlin[pair*3+2]*sc2 + sh2, 0.f);
    }

    __syncthreads();   // wt + s3s + prologue staging ready

    for (int pt = 0; pt < 4; pt++) {
        int n = n0 + pt;
        int buf = pt & 1;

        float acc0[4] = {0.f,0.f,0.f,0.f};
        float acc1[4] = {0.f,0.f,0.f,0.f};

        // ---- half 0 gather ----
        {
            float2 q2 = *(const float2*)&g_q[n*128 + 2*lane];
            float bx = PBH[0].x - q2.x*S2[0].x;
            float by = PBH[0].y - q2.y*S2[0].y;
#pragma unroll
            for (int pi = 0; pi < 16; pi++) {
                int nbr = iA[w][buf][pi];
                float h0 = hA[w][buf][pi][0], h1 = hA[w][buf][pi][1], h2 = hA[w][buf][pi][2];
                float2 k2 = *(const float2*)&g_k[nbr*128 + 2*lane];
                float u0 = fmaxf(k2.x*S2[0].x + bx + h0*PW0[0].x + h1*PW1[0].x + h2*PW2v[0].x, 0.f);
                float u1 = fmaxf(k2.y*S2[0].y + by + h0*PW0[0].y + h1*PW1[0].y + h2*PW2v[0].y, 0.f);
                uint2 ub;
                ub.x = f2tf32(u0);
                ub.y = f2tf32(u1);
                *(uint2*)&usw[pi*68 + 2*lane] = ub;
            }
        }
        __syncwarp();

        // ---- issue next-point staging loads (consumed after half-1 gather) --
        int   nidx = 0;
        float npr0 = 0.f, npr1 = 0.f, npr2 = 0.f;
        if (pt < 3 && lane < 16) {
            int pair = (n + 1)*16 + lane;
            nidx = idx[pair];
            npr0 = g_prlin[pair*3+0];
            npr1 = g_prlin[pair*3+1];
            npr2 = g_prlin[pair*3+2];
        }

        // ---- MMA half 0 ----
        {
            int ra  = gr*68 + gc;
            int rb  = (gr + 8)*68 + gc;
            int nb0 = gr*68 + gc;
            int nb1 = (8 + gr)*68 + gc;
#pragma unroll
            for (int ks = 0; ks < 8; ks++) {
                unsigned a0 = usw[ra],     a2 = usw[ra + 4];
                unsigned a1 = usw[rb],     a3 = usw[rb + 4];
                unsigned b00 = wt[nb0],    b01 = wt[nb0 + 4];
                unsigned b10 = wt[nb1],    b11 = wt[nb1 + 4];
                mma_tf32(acc0, a0, a1, a2, a3, b00, b01);
                mma_tf32(acc1, a0, a1, a2, a3, b10, b11);
                ra += 8; rb += 8; nb0 += 8; nb1 += 8;
            }
        }
        __syncwarp();

        // ---- half 1 gather ----
        {
            float2 q2 = *(const float2*)&g_q[n*128 + 64 + 2*lane];
            float bx = PBH[1].x - q2.x*S2[1].x;
            float by = PBH[1].y - q2.y*S2[1].y;
#pragma unroll
            for (int pi = 0; pi < 16; pi++) {
                int nbr = iA[w][buf][pi];
                float h0 = hA[w][buf][pi][0], h1 = hA[w][buf][pi][1], h2 = hA[w][buf][pi][2];
                float2 k2 = *(const float2*)&g_k[nbr*128 + 64 + 2*lane];
                float u0 = fmaxf(k2.x*S2[1].x + bx + h0*PW0[1].x + h1*PW1[1].x + h2*PW2v[1].x, 0.f);
                float u1 = fmaxf(k2.y*S2[1].y + by + h0*PW0[1].y + h1*PW1[1].y + h2*PW2v[1].y, 0.f);
                uint2 ub;
                ub.x = f2tf32(u0);
                ub.y = f2tf32(u1);
                *(uint2*)&usw[pi*68 + 2*lane] = ub;
            }
        }

        // ---- consume staging prefetch into other buffer ----
        if (pt < 3 && lane < 16) {
            iA[w][1-buf][lane] = nidx;
            hA[w][1-buf][lane][0] = fmaxf(npr0*sc0 + sh0, 0.f);
            hA[w][1-buf][lane][1] = fmaxf(npr1*sc1 + sh1, 0.f);
            hA[w][1-buf][lane][2] = fmaxf(npr2*sc2 + sh2, 0.f);
        }
        __syncwarp();

        // ---- MMA half 1 ----
        {
            int ra  = gr*68 + gc;
            int rb  = (gr + 8)*68 + gc;
            int nb0 = (16 + gr)*68 + gc;
            int nb1 = (16 + 8 + gr)*68 + gc;
#pragma unroll
            for (int ks = 0; ks < 8; ks++) {
                unsigned a0 = usw[ra],     a2 = usw[ra + 4];
                unsigned a1 = usw[rb],     a3 = usw[rb + 4];
                unsigned b00 = wt[nb0],    b01 = wt[nb0 + 4];
                unsigned b10 = wt[nb1],    b11 = wt[nb1 + 4];
                mma_tf32(acc0, a0, a1, a2, a3, b00, b01);
                mma_tf32(acc1, a0, a1, a2, a3, b10, b11);
                ra += 8; rb += 8; nb0 += 8; nb1 += 8;
            }
        }
        __syncwarp();   // before next iteration overwrites usw

        // ---- epilogue per point ----
#pragma unroll
        for (int nt2 = 0; nt2 < 2; nt2++) {
            float* acc = nt2 ? acc1 : acc0;
            int c0 = nt2*8 + gc*2;
            float o00 = acc[0] + bcol[nt2*2+0], o01 = acc[1] + bcol[nt2*2+1];
            float o10 = acc[2] + bcol[nt2*2+0], o11 = acc[3] + bcol[nt2*2+1];
            int pA = n*16 + gr;
            int pB = pA + 8;
            float2 oa = {o00, o01}, ob = {o10, o11};
            *(float2*)&g_w2[pA*16 + c0] = oa;
            *(float2*)&g_w2[pB*16 + c0] = ob;
            ls[nt2*2+0] += o00 + o10;  lss[nt2*2+0] += o00*o00 + o10*o10;
            ls[nt2*2+1] += o01 + o11;  lss[nt2*2+1] += o01*o01 + o11*o11;
        }
    }

    atomicAdd(&s3s[gc*2],     ls[0]);  atomicAdd(&ss3s[gc*2],     lss[0]);
    atomicAdd(&s3s[gc*2+1],   ls[1]);  atomicAdd(&ss3s[gc*2+1],   lss[1]);
    atomicAdd(&s3s[8+gc*2],   ls[2]);  atomicAdd(&ss3s[8+gc*2],   lss[2]);
    atomicAdd(&s3s[8+gc*2+1], ls[3]);  atomicAdd(&ss3s[8+gc*2+1], lss[3]);
    __syncthreads();
    if (t < CSD)        atomicAdd(&g_s3[t], s3s[t]);
    else if (t < 2*CSD) atomicAdd(&g_ss3[t-CSD], ss3s[t-CSD]);

    __syncthreads();
    __shared__ bool is_last;
    if (t == 0) {
        __threadfence();
        is_last = (atomicAdd(&g_tk3, 1u) == gridDim.x - 1);
    }
    __syncthreads();
    if (is_last && t < CSD) {
        __threadfence();
        float cnt = (float)PAIRS;
        float mean = g_s3[t] / cnt;
        float var  = g_ss3[t] / cnt - mean*mean;
        float scv  = g[t] * rsqrtf(var + FEPS);
        g_scale3[t] = scv;
        g_shift3[t] = be[t] - mean*scv;
    }
}

// ---------------- K5: bn3 + 16x16 matmul + softmax + aggregate --------------
__global__ __launch_bounds__(256)
void k_final(const int* __restrict__ idx,
             const float* __restrict__ pW2, const float* __restrict__ pb2,
             const float* __restrict__ wW2, const float* __restrict__ wb2,
             float* __restrict__ out) {
    int t = threadIdx.x;
    int half = t >> 7;
    int tl = t & 127;
    int n = blockIdx.x*2 + half;

    __shared__ float a[2][16*17];
    __shared__ float wsm[2][16*17];
    __shared__ float hs[2][16][4];
    __shared__ int   nbrs[2][16];
    __shared__ float wW2s[256];

    wW2s[t] = wW2[t];

    if (tl < 16) {
        int pair = n*16 + tl;
        nbrs[half][tl]  = idx[pair];
        hs[half][tl][0] = fmaxf(g_prlin[pair*3+0]*g_scale1[0] + g_shift1[0], 0.f);
        hs[half][tl][1] = fmaxf(g_prlin[pair*3+1]*g_scale1[1] + g_shift1[1], 0.f);
        hs[half][tl][2] = fmaxf(g_prlin[pair*3+2]*g_scale1[2] + g_shift1[2], 0.f);
    }

#pragma unroll
    for (int i = tl; i < 256; i += 128) {
        int c2 = i & 15;
        float v = g_w2[n*256 + i];
        a[half][(i >> 4)*17 + c2] = fmaxf(v*g_scale3[c2] + g_shift3[c2], 0.f);
    }
    __syncthreads();

#pragma unroll
    for (int i = tl; i < 256; i += 128) {
        int s = i >> 4, c2 = i & 15;
        float acc = wb2[c2];
#pragma unroll
        for (int j = 0; j < 16; j++) acc += a[half][s*17 + j] * wW2s[j*16 + c2];
        wsm[half][s*17 + c2] = acc;
    }
    __syncthreads();

    if (tl < 16) {
        float m = -1e30f;
#pragma unroll
        for (int s = 0; s < 16; s++) m = fmaxf(m, wsm[half][s*17 + tl]);
        float e[16]; float sum = 0.f;
#pragma unroll
        for (int s = 0; s < 16; s++) { e[s] = __expf(wsm[half][s*17 + tl] - m); sum += e[s]; }
        float inv = 1.f / sum;
#pragma unroll
        for (int s = 0; s < 16; s++) wsm[half][s*17 + tl] = e[s] * inv;
    }
    __syncthreads();

    int c = tl, c2 = tl & 15;
    float pb2c = pb2[c];
    float pw0 = pW2[c], pw1 = pW2[128 + c], pw2 = pW2[256 + c];
    float acc = 0.f;
#pragma unroll
    for (int s = 0; s < 16; s++) {
        float vv  = g_v[nbrs[half][s]*128 + c];
        float pr1 = pb2c + hs[half][s][0]*pw0 + hs[half][s][1]*pw1 + hs[half][s][2]*pw2;
        acc += (vv + pr1) * wsm[half][s*17 + c2];
    }
    out[n*128 + c] = acc;
}

// ---------------- launch -----------------------------------------------------
extern "C" void kernel_launch(void* const* d_in, const int* in_sizes, int n_in,
                              void* d_out, int out_size) {
    (void)in_sizes; (void)n_in; (void)out_size;
    const float* p    = (const float*)d_in[0];
    const float* x    = (const float*)d_in[1];
    const float* Wq   = (const float*)d_in[2];
    const float* bq   = (const float*)d_in[3];
    const float* Wk   = (const float*)d_in[4];
    const float* bk   = (const float*)d_in[5];
    const float* Wv   = (const float*)d_in[6];
    const float* bv   = (const float*)d_in[7];
    const float* pW1  = (const float*)d_in[8];
    const float* pb1  = (const float*)d_in[9];
    const float* pg1  = (const float*)d_in[10];
    const float* pbe1 = (const float*)d_in[11];
    const float* pW2  = (const float*)d_in[12];
    const float* pb2  = (const float*)d_in[13];
    const float* wg1  = (const float*)d_in[14];
    const float* wbe1 = (const float*)d_in[15];
    const float* wW1  = (const float*)d_in[16];
    const float* wb1  = (const float*)d_in[17];
    const float* wg2  = (const float*)d_in[18];
    const float* wbe2 = (const float*)d_in[19];
    const float* wW2  = (const float*)d_in[20];
    const float* wb2  = (const float*)d_in[21];
    const int*   idx  = (const int*)  d_in[22];
    float* out = (float*)d_out;

    k_proj_mma<<<dim3(NPTS/64, 3), 128>>>(x, Wq, bq, Wk, bk, Wv, bv);    // 1 (+zero)
    k_prlin<<<512, 256>>>(p, idx, pW1, pb1, pg1, pbe1);                  // 2
    k_bn2stats<<<2048, 256>>>(idx, pW2, pb2, wg1, wbe1);                 // 3
    k_w2<<<2048, 128>>>(idx, pW2, pb2, wW1, wb1, wg2, wbe2);             // 4 <- profiled
    k_final<<<NPTS/2, 256>>>(idx, pW2, pb2, wW2, wb2, out);              // 5
}

// round 17
// speedup vs baseline: 1.2403x; 1.2403x over previous
#include <cuda_runtime.h>

#define NPTS 32768
#define CDIM 128
#define NSAM 16
#define CSD  16
#define PAIRS (NPTS*NSAM)
#define FEPS 1e-5f

// ---------------- scratch (device globals; no allocation allowed) ----------
__device__ float g_q[NPTS*CDIM];
__device__ float g_k[NPTS*CDIM];
__device__ float g_v[NPTS*CDIM];
__device__ float g_prlin[PAIRS*3];
__device__ float g_w2[PAIRS*CSD];

__device__ float g_s1[3],    g_ss1[3],    g_scale1[3],    g_shift1[3];
__device__ float g_s2[CDIM], g_ss2[CDIM], g_scale2[CDIM], g_shift2[CDIM];
__device__ float g_s3[CSD],  g_ss3[CSD],  g_scale3[CSD],  g_shift3[CSD];
__device__ unsigned g_tk1, g_tk2, g_tk3;

__device__ __forceinline__ unsigned f2tf32(float v) {
    unsigned r; asm("cvt.rna.tf32.f32 %0, %1;" : "=r"(r) : "f"(v)); return r;
}
__device__ __forceinline__ void mma_tf32(float* acc, unsigned a0, unsigned a1,
                                         unsigned a2, unsigned a3,
                                         unsigned b0, unsigned b1) {
    asm volatile(
        "mma.sync.aligned.m16n8k8.row.col.f32.tf32.tf32.f32 "
        "{%0,%1,%2,%3}, {%4,%5,%6,%7}, {%8,%9}, {%0,%1,%2,%3};"
        : "+f"(acc[0]), "+f"(acc[1]), "+f"(acc[2]), "+f"(acc[3])
        : "r"(a0), "r"(a1), "r"(a2), "r"(a3), "r"(b0), "r"(b1));
}

// ---------------- K1: q,k,v projections via tf32 mma (single-pass all) ------
__global__ __launch_bounds__(128)
void k_proj_mma(const float* __restrict__ x,
                const float* __restrict__ Wq, const float* __restrict__ bq,
                const float* __restrict__ Wk, const float* __restrict__ bk,
                const float* __restrict__ Wv, const float* __restrict__ bv) {
    if (blockIdx.x == 0 && blockIdx.y == 0) {
        int tt = threadIdx.x;
        if (tt < 3)    { g_s1[tt] = 0.f; g_ss1[tt] = 0.f; }
        if (tt < CDIM) { g_s2[tt] = 0.f; g_ss2[tt] = 0.f; }
        if (tt < CSD)  { g_s3[tt] = 0.f; g_ss3[tt] = 0.f; }
        if (tt == 0) { g_tk1 = 0; g_tk2 = 0; g_tk3 = 0; }
    }

    const float* W; const float* b; float* out;
    if (blockIdx.y == 0)      { W = Wq; b = bq; out = g_q; }
    else if (blockIdx.y == 1) { W = Wk; b = bk; out = g_k; }
    else                      { W = Wv; b = bv; out = g_v; }

    __shared__ unsigned xs_hi[64*20];
    __shared__ unsigned ws_hi[128*20];

    int t = threadIdx.x;
    int lane = t & 31, w = t >> 5;
    int row0 = blockIdx.x * 64;
    int gr = lane >> 2;
    int gc = lane & 3;

    float acc[16][4];
#pragma unroll
    for (int nt = 0; nt < 16; nt++)
#pragma unroll
        for (int j = 0; j < 4; j++) acc[nt][j] = 0.f;

    for (int kb = 0; kb < 128; kb += 16) {
#pragma unroll
        for (int e = t; e < 64*16; e += 128) {
            int r = e >> 4, k = e & 15;
            xs_hi[r*20 + k] = f2tf32(x[(row0 + r)*128 + kb + k]);
        }
#pragma unroll
        for (int e = t; e < 128*16; e += 128) {
            int k = e >> 7, n = e & 127;
            ws_hi[n*20 + k] = f2tf32(W[(kb + k)*128 + n]);
        }
        __syncthreads();

#pragma unroll
        for (int ks = 0; ks < 2; ks++) {
            int k0 = ks*8;
            int ra = (w*16 + gr)*20 + k0 + gc;
            int rb = (w*16 + gr + 8)*20 + k0 + gc;
            unsigned ah0 = xs_hi[ra],     ah1 = xs_hi[rb];
            unsigned ah2 = xs_hi[ra + 4], ah3 = xs_hi[rb + 4];
#pragma unroll
            for (int nt = 0; nt < 16; nt++) {
                int nb = (nt*8 + gr)*20 + k0 + gc;
                unsigned bh0 = ws_hi[nb], bh1 = ws_hi[nb + 4];
                mma_tf32(acc[nt], ah0, ah1, ah2, ah3, bh0, bh1);
            }
        }
        __syncthreads();
    }

    int r0 = row0 + w*16 + gr;
#pragma unroll
    for (int nt = 0; nt < 16; nt++) {
        int col = nt*8 + gc*2;
        float b0v = b[col], b1v = b[col+1];
        float2 o0 = {acc[nt][0] + b0v, acc[nt][1] + b1v};
        float2 o1 = {acc[nt][2] + b0v, acc[nt][3] + b1v};
        *(float2*)&out[r0*128 + col]     = o0;
        *(float2*)&out[(r0+8)*128 + col] = o1;
    }
}

// ---------------- K2: prlin + BN1 stats + fused finalize --------------------
__global__ void k_prlin(const float* __restrict__ p, const int* __restrict__ idx,
                        const float* __restrict__ pW1, const float* __restrict__ pb1,
                        const float* __restrict__ g, const float* __restrict__ be) {
    float w00 = pW1[0], w01 = pW1[1], w02 = pW1[2];
    float w10 = pW1[3], w11 = pW1[4], w12 = pW1[5];
    float w20 = pW1[6], w21 = pW1[7], w22 = pW1[8];
    float b0 = pb1[0], b1 = pb1[1], b2 = pb1[2];

    float s[3]  = {0.f, 0.f, 0.f};
    float ss[3] = {0.f, 0.f, 0.f};

    int stride = gridDim.x * blockDim.x;
    for (int pair = blockIdx.x*blockDim.x + threadIdx.x; pair < PAIRS; pair += stride) {
        int n   = pair >> 4;
        int nbr = idx[pair];
        float d0 = p[nbr*3+0] - p[n*3+0];
        float d1 = p[nbr*3+1] - p[n*3+1];
        float d2 = p[nbr*3+2] - p[n*3+2];
        float v0 = b0 + d0*w00 + d1*w10 + d2*w20;
        float v1 = b1 + d0*w01 + d1*w11 + d2*w21;
        float v2 = b2 + d0*w02 + d1*w12 + d2*w22;
        g_prlin[pair*3+0] = v0;
        g_prlin[pair*3+1] = v1;
        g_prlin[pair*3+2] = v2;
        s[0] += v0; ss[0] += v0*v0;
        s[1] += v1; ss[1] += v1*v1;
        s[2] += v2; ss[2] += v2*v2;
    }

#pragma unroll
    for (int o = 16; o > 0; o >>= 1) {
#pragma unroll
        for (int j = 0; j < 3; j++) {
            s[j]  += __shfl_down_sync(0xffffffffu, s[j],  o);
            ss[j] += __shfl_down_sync(0xffffffffu, ss[j], o);
        }
    }
    __shared__ float part[8][6];
    int lane = threadIdx.x & 31, w = threadIdx.x >> 5;
    if (lane == 0) {
        part[w][0] = s[0];  part[w][1] = s[1];  part[w][2] = s[2];
        part[w][3] = ss[0]; part[w][4] = ss[1]; part[w][5] = ss[2];
    }
    __syncthreads();
    if (threadIdx.x < 6) {
        float tot = 0.f;
#pragma unroll
        for (int ww = 0; ww < 8; ww++) tot += part[ww][threadIdx.x];
        if (threadIdx.x < 3) atomicAdd(&g_s1[threadIdx.x], tot);
        else                 atomicAdd(&g_ss1[threadIdx.x - 3], tot);
    }
    __syncthreads();
    __shared__ bool is_last;
    if (threadIdx.x == 0) {
        __threadfence();
        is_last = (atomicAdd(&g_tk1, 1u) == gridDim.x - 1);
    }
    __syncthreads();
    if (is_last && threadIdx.x < 3) {
        __threadfence();
        int c = threadIdx.x;
        float cnt = (float)PAIRS;
        float mean = g_s1[c] / cnt;
        float var  = g_ss1[c] / cnt - mean*mean;
        float scv  = g[c] * rsqrtf(var + FEPS);
        g_scale1[c] = scv;
        g_shift1[c] = be[c] - mean*scv;
    }
}

// ---------------- K3: BN2 stats ----------------------------------------------
__global__ __launch_bounds__(256, 5)
void k_bn2stats(const int* __restrict__ idx,
                const float* __restrict__ pW2, const float* __restrict__ pb2,
                const float* __restrict__ g, const float* __restrict__ be) {
    int t = threadIdx.x, lane = t & 31, w = t >> 5;
    int wg = blockIdx.x*8 + w;
    int base = wg*32;

    __shared__ float hsm[8][32][3];
    __shared__ int   ism[8][32];

    float4 pw0  = *(const float4*)&pW2[0*CDIM + lane*4];
    float4 pw1  = *(const float4*)&pW2[1*CDIM + lane*4];
    float4 pw2v = *(const float4*)&pW2[2*CDIM + lane*4];
    float4 pbv  = *(const float4*)&pb2[lane*4];
    float sc0 = g_scale1[0], sc1 = g_scale1[1], sc2 = g_scale1[2];
    float sh0 = g_shift1[0], sh1 = g_shift1[1], sh2 = g_shift1[2];

    {
        int pair = base + lane;
        ism[w][lane] = idx[pair];
        hsm[w][lane][0] = fmaxf(g_prlin[pair*3+0]*sc0 + sh0, 0.f);
        hsm[w][lane][1] = fmaxf(g_prlin[pair*3+1]*sc1 + sh1, 0.f);
        hsm[w][lane][2] = fmaxf(g_prlin[pair*3+2]*sc2 + sh2, 0.f);
    }
    __syncwarp();

    const float4* kp = (const float4*)g_k;
    const float4* qp = (const float4*)g_q;

    float4 s4  = {0.f,0.f,0.f,0.f};
    float4 q4s = {0.f,0.f,0.f,0.f};

#pragma unroll
    for (int np = 0; np < 2; np++) {
        int n = (base >> 4) + np;
        float4 qq = qp[n*32 + lane];
        float4 b4;
        b4.x = pbv.x - qq.x; b4.y = pbv.y - qq.y;
        b4.z = pbv.z - qq.z; b4.w = pbv.w - qq.w;
#pragma unroll
        for (int s = 0; s < 16; s++) {
            int i   = np*16 + s;
            int nbr = ism[w][i];
            float h0 = hsm[w][i][0], h1 = hsm[w][i][1], h2 = hsm[w][i][2];
            float4 kk = kp[nbr*32 + lane];
            float wx = kk.x + b4.x + h0*pw0.x + h1*pw1.x + h2*pw2v.x;
            float wy = kk.y + b4.y + h0*pw0.y + h1*pw1.y + h2*pw2v.y;
            float wz = kk.z + b4.z + h0*pw0.z + h1*pw1.z + h2*pw2v.z;
            float ww = kk.w + b4.w + h0*pw0.w + h1*pw1.w + h2*pw2v.w;
            s4.x += wx; q4s.x += wx*wx;
            s4.y += wy; q4s.y += wy*wy;
            s4.z += wz; q4s.z += wz*wz;
            s4.w += ww; q4s.w += ww*ww;
        }
    }

    __shared__ float red[8][256];
    red[w][lane*4+0]     = s4.x;  red[w][lane*4+1]     = s4.y;
    red[w][lane*4+2]     = s4.z;  red[w][lane*4+3]     = s4.w;
    red[w][128+lane*4+0] = q4s.x; red[w][128+lane*4+1] = q4s.y;
    red[w][128+lane*4+2] = q4s.z; red[w][128+lane*4+3] = q4s.w;
    __syncthreads();
    float tot = 0.f;
#pragma unroll
    for (int ww = 0; ww < 8; ww++) tot += red[ww][t];
    if (t < 128) atomicAdd(&g_s2[t], tot);
    else         atomicAdd(&g_ss2[t-128], tot);

    __syncthreads();
    __shared__ bool is_last;
    if (t == 0) {
        __threadfence();
        is_last = (atomicAdd(&g_tk2, 1u) == gridDim.x - 1);
    }
    __syncthreads();
    if (is_last && t < CDIM) {
        __threadfence();
        float cnt = (float)PAIRS;
        float mean = g_s2[t] / cnt;
        float var  = g_ss2[t] / cnt - mean*mean;
        float scv  = g[t] * rsqrtf(var + FEPS);
        g_scale2[t] = scv;
        g_shift2[t] = be[t] - mean*scv;
    }
}

// ---------------- K4 (PROFILED): w2 — R15 form (measured best 104.6us) ------
__global__ __launch_bounds__(128, 7)
void k_w2(const int* __restrict__ idx,
          const float* __restrict__ pW2, const float* __restrict__ pb2,
          const float* __restrict__ wW1, const float* __restrict__ wb1,
          const float* __restrict__ g, const float* __restrict__ be) {
    __shared__ unsigned us[4*16*68];
    __shared__ unsigned wt[2*16*68];
    __shared__ float hA[4][16][3];
    __shared__ int   iA[4][16];
    __shared__ float s3s[CSD], ss3s[CSD];

    int t = threadIdx.x, lane = t & 31, w = t >> 5;
    int gr = lane >> 2, gc = lane & 3;

    for (int e = t; e < 128*16; e += 128) {
        int c = e >> 4, j = e & 15;
        int h = c >> 6, cp = c & 63;
        wt[(h*16 + j)*68 + cp] = f2tf32(wW1[e]);
    }
    if (t < CSD) { s3s[t] = 0.f; ss3s[t] = 0.f; }

    float2 PW0[2], PW1[2], PW2v[2], S2[2], PBH[2];
#pragma unroll
    for (int h = 0; h < 2; h++) {
        int c = h*64 + 2*lane;
        float2 s2 = *(const float2*)&g_scale2[c];
        float2 a;
        S2[h] = s2;
        a = *(const float2*)&pW2[0*CDIM + c];
        PW0[h] = make_float2(a.x*s2.x, a.y*s2.y);
        a = *(const float2*)&pW2[1*CDIM + c];
        PW1[h] = make_float2(a.x*s2.x, a.y*s2.y);
        a = *(const float2*)&pW2[2*CDIM + c];
        PW2v[h] = make_float2(a.x*s2.x, a.y*s2.y);
        float2 pb = *(const float2*)&pb2[c];
        float2 h2 = *(const float2*)&g_shift2[c];
        PBH[h] = make_float2(pb.x*s2.x + h2.x, pb.y*s2.y + h2.y);
    }
    float sc0 = g_scale1[0], sc1 = g_scale1[1], sc2 = g_scale1[2];
    float sh0 = g_shift1[0], sh1 = g_shift1[1], sh2 = g_shift1[2];

    float bcol[4];
    bcol[0] = wb1[gc*2];     bcol[1] = wb1[gc*2+1];
    bcol[2] = wb1[8+gc*2];   bcol[3] = wb1[8+gc*2+1];
    float ls[4]  = {0.f,0.f,0.f,0.f};
    float lss[4] = {0.f,0.f,0.f,0.f};

    unsigned* usw = &us[w*16*68];

    __syncthreads();

    for (int pt = 0; pt < 4; pt++) {
        int n = blockIdx.x*16 + w*4 + pt;

        if (lane < 16) {
            int pair = n*16 + lane;
            iA[w][lane] = idx[pair];
            hA[w][lane][0] = fmaxf(g_prlin[pair*3+0]*sc0 + sh0, 0.f);
            hA[w][lane][1] = fmaxf(g_prlin[pair*3+1]*sc1 + sh1, 0.f);
            hA[w][lane][2] = fmaxf(g_prlin[pair*3+2]*sc2 + sh2, 0.f);
        }
        __syncwarp();

        float acc0[4] = {0.f,0.f,0.f,0.f};
        float acc1[4] = {0.f,0.f,0.f,0.f};

#pragma unroll
        for (int h = 0; h < 2; h++) {
            {
                float2 q2 = *(const float2*)&g_q[n*128 + h*64 + 2*lane];
                float bx = PBH[h].x - q2.x*S2[h].x;
                float by = PBH[h].y - q2.y*S2[h].y;
#pragma unroll
                for (int pi = 0; pi < 16; pi++) {
                    int nbr = iA[w][pi];
                    float h0 = hA[w][pi][0], h1 = hA[w][pi][1], h2 = hA[w][pi][2];
                    float2 k2 = *(const float2*)&g_k[nbr*128 + h*64 + 2*lane];
                    float u0 = fmaxf(k2.x*S2[h].x + bx + h0*PW0[h].x + h1*PW1[h].x + h2*PW2v[h].x, 0.f);
                    float u1 = fmaxf(k2.y*S2[h].y + by + h0*PW0[h].y + h1*PW1[h].y + h2*PW2v[h].y, 0.f);
                    uint2 ub;
                    ub.x = f2tf32(u0);
                    ub.y = f2tf32(u1);
                    *(uint2*)&usw[pi*68 + 2*lane] = ub;
                }
            }
            __syncwarp();

            {
                int ra  = gr*68 + gc;
                int rb  = (gr + 8)*68 + gc;
                int nb0 = (h*16 + gr)*68 + gc;
                int nb1 = (h*16 + 8 + gr)*68 + gc;
#pragma unroll
                for (int ks = 0; ks < 8; ks++) {
                    unsigned a0 = usw[ra],     a2 = usw[ra + 4];
                    unsigned a1 = usw[rb],     a3 = usw[rb + 4];
                    unsigned b00 = wt[nb0],    b01 = wt[nb0 + 4];
                    unsigned b10 = wt[nb1],    b11 = wt[nb1 + 4];
                    mma_tf32(acc0, a0, a1, a2, a3, b00, b01);
                    mma_tf32(acc1, a0, a1, a2, a3, b10, b11);
                    ra += 8; rb += 8; nb0 += 8; nb1 += 8;
                }
            }
            __syncwarp();
        }

#pragma unroll
        for (int nt2 = 0; nt2 < 2; nt2++) {
            float* acc = nt2 ? acc1 : acc0;
            int c0 = nt2*8 + gc*2;
            float o00 = acc[0] + bcol[nt2*2+0], o01 = acc[1] + bcol[nt2*2+1];
            float o10 = acc[2] + bcol[nt2*2+0], o11 = acc[3] + bcol[nt2*2+1];
            int pA = n*16 + gr;
            int pB = pA + 8;
            float2 oa = {o00, o01}, ob = {o10, o11};
            *(float2*)&g_w2[pA*16 + c0] = oa;
            *(float2*)&g_w2[pB*16 + c0] = ob;
            ls[nt2*2+0] += o00 + o10;  lss[nt2*2+0] += o00*o00 + o10*o10;
            ls[nt2*2+1] += o01 + o11;  lss[nt2*2+1] += o01*o01 + o11*o11;
        }
    }

    atomicAdd(&s3s[gc*2],     ls[0]);  atomicAdd(&ss3s[gc*2],     lss[0]);
    atomicAdd(&s3s[gc*2+1],   ls[1]);  atomicAdd(&ss3s[gc*2+1],   lss[1]);
    atomicAdd(&s3s[8+gc*2],   ls[2]);  atomicAdd(&ss3s[8+gc*2],   lss[2]);
    atomicAdd(&s3s[8+gc*2+1], ls[3]);  atomicAdd(&ss3s[8+gc*2+1], lss[3]);
    __syncthreads();
    if (t < CSD)        atomicAdd(&g_s3[t], s3s[t]);
    else if (t < 2*CSD) atomicAdd(&g_ss3[t-CSD], ss3s[t-CSD]);

    __syncthreads();
    __shared__ bool is_last;
    if (t == 0) {
        __threadfence();
        is_last = (atomicAdd(&g_tk3, 1u) == gridDim.x - 1);
    }
    __syncthreads();
    if (is_last && t < CSD) {
        __threadfence();
        float cnt = (float)PAIRS;
        float mean = g_s3[t] / cnt;
        float var  = g_ss3[t] / cnt - mean*mean;
        float scv  = g[t] * rsqrtf(var + FEPS);
        g_scale3[t] = scv;
        g_shift3[t] = be[t] - mean*scv;
    }
}

// ---------------- K5: k_final warp-autonomous — warp = point, no block sync -
// block 256 (8 warps), grid NPTS/8. Per warp: stage idx/h, bn3+relu a-tile,
// 16x16 matmul, softmax, v-gather aggregate. Only warp-level syncs.
__global__ __launch_bounds__(256)
void k_final(const int* __restrict__ idx,
             const float* __restrict__ pW2, const float* __restrict__ pb2,
             const float* __restrict__ wW2, const float* __restrict__ wb2,
             float* __restrict__ out) {
    __shared__ float aW[8][16*17];    // bn3(relu(w2)) tile, stride 17
    __shared__ float wsW[8][16*20];   // attention weights, stride 20 (f4-aligned)
    __shared__ float hF[8][16][4];
    __shared__ int   iF[8][16];
    __shared__ float wW2s[256];

    int t = threadIdx.x, lane = t & 31, w = t >> 5;
    int n = blockIdx.x*8 + w;

    wW2s[t] = wW2[t];
    __syncthreads();   // wW2s staged once; only block sync in kernel

    // stage idx/h (lanes 0-15)
    if (lane < 16) {
        int pair = n*16 + lane;
        iF[w][lane]    = idx[pair];
        hF[w][lane][0] = fmaxf(g_prlin[pair*3+0]*g_scale1[0] + g_shift1[0], 0.f);
        hF[w][lane][1] = fmaxf(g_prlin[pair*3+1]*g_scale1[1] + g_shift1[1], 0.f);
        hF[w][lane][2] = fmaxf(g_prlin[pair*3+2]*g_scale1[2] + g_shift1[2], 0.f);
    }

    // load w2 row: 8 values per lane, bn3 + relu -> aW
    {
        int s  = lane >> 1;
        int cb = 8*(lane & 1);
        float4 v0 = *(const float4*)&g_w2[n*256 + lane*8];
        float4 v1 = *(const float4*)&g_w2[n*256 + lane*8 + 4];
        float4 s3a = *(const float4*)&g_scale3[cb];
        float4 s3b = *(const float4*)&g_scale3[cb+4];
        float4 h3a = *(const float4*)&g_shift3[cb];
        float4 h3b = *(const float4*)&g_shift3[cb+4];
        float* ap = &aW[w][s*17 + cb];
        ap[0] = fmaxf(v0.x*s3a.x + h3a.x, 0.f);
        ap[1] = fmaxf(v0.y*s3a.y + h3a.y, 0.f);
        ap[2] = fmaxf(v0.z*s3a.z + h3a.z, 0.f);
        ap[3] = fmaxf(v0.w*s3a.w + h3a.w, 0.f);
        ap[4] = fmaxf(v1.x*s3b.x + h3b.x, 0.f);
        ap[5] = fmaxf(v1.y*s3b.y + h3b.y, 0.f);
        ap[6] = fmaxf(v1.z*s3b.z + h3b.z, 0.f);
        ap[7] = fmaxf(v1.w*s3b.w + h3b.w, 0.f);
    }
    __syncwarp();

    // matmul: lane computes 8 outputs (s = lane>>1, c2 in [8*(lane&1), +8))
    {
        int s  = lane >> 1;
        int cb = 8*(lane & 1);
        float4 acc0 = *(const float4*)&wb2[cb];
        float4 acc1 = *(const float4*)&wb2[cb+4];
#pragma unroll
        for (int k = 0; k < 16; k++) {
            float av = aW[w][s*17 + k];
            float4 w0 = *(const float4*)&wW2s[k*16 + cb];
            float4 w1 = *(const float4*)&wW2s[k*16 + cb + 4];
            acc0.x += av*w0.x; acc0.y += av*w0.y;
            acc0.z += av*w0.z; acc0.w += av*w0.w;
            acc1.x += av*w1.x; acc1.y += av*w1.y;
            acc1.z += av*w1.z; acc1.w += av*w1.w;
        }
        *(float4*)&wsW[w][s*20 + cb]     = acc0;
        *(float4*)&wsW[w][s*20 + cb + 4] = acc1;
    }
    __syncwarp();

    // softmax over s (lanes 0-15, one c2 each)
    if (lane < 16) {
        float m = -1e30f;
#pragma unroll
        for (int s = 0; s < 16; s++) m = fmaxf(m, wsW[w][s*20 + lane]);
        float e[16]; float sum = 0.f;
#pragma unroll
        for (int s = 0; s < 16; s++) { e[s] = __expf(wsW[w][s*20 + lane] - m); sum += e[s]; }
        float inv = 1.f / sum;
#pragma unroll
        for (int s = 0; s < 16; s++) wsW[w][s*20 + lane] = e[s] * inv;
    }
    __syncwarp();

    // aggregate: lane owns 4 channels c = lane*4 .. +3
    {
        int c0 = lane*4;
        int c2g = 4*(lane & 3);
        float4 pb  = *(const float4*)&pb2[c0];
        float4 pw0 = *(const float4*)&pW2[c0];
        float4 pw1 = *(const float4*)&pW2[128 + c0];
        float4 pw2 = *(const float4*)&pW2[256 + c0];
        float4 acc = {0.f, 0.f, 0.f, 0.f};
#pragma unroll
        for (int s = 0; s < 16; s++) {
            int nbr = iF[w][s];
            float h0 = hF[w][s][0], h1 = hF[w][s][1], h2 = hF[w][s][2];
            float4 vv = *(const float4*)&g_v[nbr*128 + c0];
            float4 ws = *(const float4*)&wsW[w][s*20 + c2g];
            float p0 = pb.x + h0*pw0.x + h1*pw1.x + h2*pw2.x;
            float p1 = pb.y + h0*pw0.y + h1*pw1.y + h2*pw2.y;
            float p2 = pb.z + h0*pw0.z + h1*pw1.z + h2*pw2.z;
            float p3 = pb.w + h0*pw0.w + h1*pw1.w + h2*pw2.w;
            acc.x += (vv.x + p0) * ws.x;
            acc.y += (vv.y + p1) * ws.y;
            acc.z += (vv.z + p2) * ws.z;
            acc.w += (vv.w + p3) * ws.w;
        }
        *(float4*)&out[n*128 + c0] = acc;
    }
}

// ---------------- launch -----------------------------------------------------
extern "C" void kernel_launch(void* const* d_in, const int* in_sizes, int n_in,
                              void* d_out, int out_size) {
    (void)in_sizes; (void)n_in; (void)out_size;
    const float* p    = (const float*)d_in[0];
    const float* x    = (const float*)d_in[1];
    const float* Wq   = (const float*)d_in[2];
    const float* bq   = (const float*)d_in[3];
    const float* Wk   = (const float*)d_in[4];
    const float* bk   = (const float*)d_in[5];
    const float* Wv   = (const float*)d_in[6];
    const float* bv   = (const float*)d_in[7];
    const float* pW1  = (const float*)d_in[8];
    const float* pb1  = (const float*)d_in[9];
    const float* pg1  = (const float*)d_in[10];
    const float* pbe1 = (const float*)d_in[11];
    const float* pW2  = (const float*)d_in[12];
    const float* pb2  = (const float*)d_in[13];
    const float* wg1  = (const float*)d_in[14];
    const float* wbe1 = (const float*)d_in[15];
    const float* wW1  = (const float*)d_in[16];
    const float* wb1  = (const float*)d_in[17];
    const float* wg2  = (const float*)d_in[18];
    const float* wbe2 = (const float*)d_in[19];
    const float* wW2  = (const float*)d_in[20];
    const float* wb2  = (const float*)d_in[21];
    const int*   idx  = (const int*)  d_in[22];
    float* out = (float*)d_out;

    k_proj_mma<<<dim3(NPTS/64, 3), 128>>>(x, Wq, bq, Wk, bk, Wv, bv);    // 1 (+zero)
    k_prlin<<<512, 256>>>(p, idx, pW1, pb1, pg1, pbe1);                  // 2
    k_bn2stats<<<2048, 256>>>(idx, pW2, pb2, wg1, wbe1);                 // 3
    k_w2<<<2048, 128>>>(idx, pW2, pb2, wW1, wb1, wg2, wbe2);             // 4 <- profiled
    k_final<<<NPTS/8, 256>>>(idx, pW2, pb2, wW2, wb2, out);              // 5
}